// round 14
// baseline (speedup 1.0000x reference)
#include <cuda_runtime.h>
#include <cuda_fp16.h>
#include <cstdint>
#include <mma.h>
#include <math.h>

using namespace nvcuda;

#define CCH 512
#define GRP 32
#define AREA 4096
#define BATCH 4
#define EPS 1e-6f

// ---------------- scratch (device globals) ----------------
__device__ __half g_xn  [(size_t)BATCH * CCH * AREA];
__device__ __half g_qkv [(size_t)BATCH * 3 * CCH * AREA];
__device__ __half g_h   [(size_t)BATCH * CCH * AREA];
__device__ float  g_s   [(size_t)BATCH * AREA * AREA];
__device__ __half g_p   [(size_t)BATCH * AREA * AREA];
__device__ __half g_wqkv[3 * CCH * CCH];
__device__ __half g_wo  [CCH * CCH];
__device__ float  g_bqkv[3 * CCH];

// ---------------- GroupNorm -> half output ----------------
__global__ void groupnorm_kernel(const float* __restrict__ net,
                                 const float* __restrict__ gscale,
                                 const float* __restrict__ gbias,
                                 __half* __restrict__ xn) {
    const int CPG = CCH / GRP;
    const int NEL = CPG * AREA;
    int bg = blockIdx.x;
    int b = bg / GRP, g = bg % GRP;
    const float* x = net + ((size_t)b * CCH + (size_t)g * CPG) * AREA;
    __half* y = xn + ((size_t)b * CCH + (size_t)g * CPG) * AREA;

    int tid = threadIdx.x;
    float s = 0.f, ss = 0.f;
    for (int i = tid; i < NEL; i += blockDim.x) {
        float v = x[i];
        s += v; ss += v * v;
    }
    __shared__ float rs[256], rss[256];
    rs[tid] = s; rss[tid] = ss;
    __syncthreads();
    for (int o = 128; o > 0; o >>= 1) {
        if (tid < o) { rs[tid] += rs[tid + o]; rss[tid] += rss[tid + o]; }
        __syncthreads();
    }
    float mu  = rs[0] / (float)NEL;
    float var = rss[0] / (float)NEL - mu * mu;
    float inv = rsqrtf(var + EPS);

    for (int i = tid; i < NEL; i += blockDim.x) {
        int cl = i / AREA;
        int c  = g * CPG + cl;
        y[i] = __float2half((x[i] - mu) * inv * gscale[c] + gbias[c]);
    }
}

// ---------------- pack weights -> half ----------------
__global__ void pack_kernel(const float* __restrict__ wq, const float* __restrict__ wk,
                            const float* __restrict__ wv, const float* __restrict__ wo,
                            const float* __restrict__ bq, const float* __restrict__ bk,
                            const float* __restrict__ bv,
                            __half* __restrict__ w, __half* __restrict__ woh,
                            float* __restrict__ b) {
    int i = blockIdx.x * blockDim.x + threadIdx.x;
    const int WN = CCH * CCH;
    if (i < WN) {
        w[i]          = __float2half(wq[i]);
        w[i + WN]     = __float2half(wk[i]);
        w[i + 2 * WN] = __float2half(wv[i]);
        woh[i]        = __float2half(wo[i]);
    }
    if (i < CCH) {
        b[i] = bq[i];
        b[i + CCH] = bk[i];
        b[i + 2 * CCH] = bv[i];
    }
}

// ---------------- 4-stage cp.async FP16 WMMA GEMM, 128x256x32, 8 warps 64x64 ----
// D[m,n] = alpha*sum_k A(m,k)*B(k,n) [+bias[m]] [+res], fp32 accumulate.
// A_COL: A(m,k)=A[k*LDA+m]; B_COL: B(k,n)=B[n*LDB+k]. OUT_HALF: C half else float.
#define BM 128
#define BN 256
#define BK 32
#define NSTAGE 4

template<bool C_> struct CondLay;
template<> struct CondLay<false> { using type = wmma::row_major; };
template<> struct CondLay<true>  { using type = wmma::col_major; };

__device__ __forceinline__ void cp16(void* s, const void* g) {
    unsigned int sa = (unsigned int)__cvta_generic_to_shared(s);
    asm volatile("cp.async.cg.shared.global [%0], [%1], 16;" :: "r"(sa), "l"(g));
}

template<bool A_COL, bool B_COL>
struct SmemSize {
    static constexpr int A_ELEMS = A_COL ? BK * 136 : BM * 40;    // halves
    static constexpr int B_ELEMS = B_COL ? BN * 40  : BK * 264;   // halves
    static constexpr int STAGE   = A_ELEMS + B_ELEMS;
    static constexpr int BYTES_PIPE = NSTAGE * STAGE * 2;
    static constexpr int BYTES_EPI  = 128 * 132 * 4;              // 67584
    static constexpr int BYTES = BYTES_PIPE > BYTES_EPI ? BYTES_PIPE : BYTES_EPI;
};

template<int Kv, int LDA, int LDB, int LDC,
         bool A_COL, bool B_COL, bool HAS_BIAS, bool HAS_RES, bool OUT_HALF>
__global__ void __launch_bounds__(256)
gemm_fp16(const __half* __restrict__ A, const __half* __restrict__ B,
          void* __restrict__ Cv,
          const float* __restrict__ bias, const float* __restrict__ res,
          long strA, long strB, long strC, long strR, float alpha) {
    extern __shared__ __align__(16) char smem_raw[];
    __half* hm = (__half*)smem_raw;
    constexpr int A_ELEMS = SmemSize<A_COL, B_COL>::A_ELEMS;
    constexpr int STAGE   = SmemSize<A_COL, B_COL>::STAGE;
    constexpr int KT      = Kv / BK;

    const int bz = blockIdx.z;
    A += (size_t)bz * strA;
    B += (size_t)bz * strB;
    if (HAS_RES) res += (size_t)bz * strR;

    const int bm = blockIdx.y * BM;
    const int bn = blockIdx.x * BN;
    const int tid = threadIdx.x;
    const int warp = tid >> 5;
    const int wm = warp >> 2;        // 0..1 : m-offset 64
    const int wn = warp & 3;         // 0..3 : n-offset 64

    wmma::fragment<wmma::accumulator, 16, 16, 16, float> acc[4][4];
    #pragma unroll
    for (int i = 0; i < 4; i++)
        #pragma unroll
        for (int j = 0; j < 4; j++)
            wmma::fill_fragment(acc[i][j], 0.0f);

    auto load_tiles = [&](int slot, int k0) {
        __half* sA = hm + slot * STAGE;
        __half* sB = sA + A_ELEMS;
        if (A_COL) {
            // [BK=32 rows][BM+8=136] -> 512 chunks
            #pragma unroll
            for (int c = tid; c < 512; c += 256) {
                int k = c >> 4, m8 = (c & 15) << 3;
                cp16(&sA[k * 136 + m8], &A[(size_t)(k0 + k) * LDA + bm + m8]);
            }
        } else {
            // [BM=128 rows][BK+8=40] -> 512 chunks
            #pragma unroll
            for (int c = tid; c < 512; c += 256) {
                int m = c >> 2, k8 = (c & 3) << 3;
                cp16(&sA[m * 40 + k8], &A[(size_t)(bm + m) * LDA + k0 + k8]);
            }
        }
        if (B_COL) {
            // [BN=256 rows][BK+8=40] -> 1024 chunks
            #pragma unroll
            for (int c = tid; c < 1024; c += 256) {
                int n = c >> 2, k8 = (c & 3) << 3;
                cp16(&sB[n * 40 + k8], &B[(size_t)(bn + n) * LDB + k0 + k8]);
            }
        } else {
            // [BK=32 rows][BN+8=264] -> 1024 chunks
            #pragma unroll
            for (int c = tid; c < 1024; c += 256) {
                int k = c >> 5, n8 = (c & 31) << 3;
                cp16(&sB[k * 264 + n8], &B[(size_t)(k0 + k) * LDB + bn + n8]);
            }
        }
    };

    // prologue: NSTAGE-1 stages in flight
    #pragma unroll
    for (int s = 0; s < NSTAGE - 1; s++) {
        if (s < KT) load_tiles(s, s * BK);
        asm volatile("cp.async.commit_group;");
    }

    using ALay = typename CondLay<A_COL>::type;
    using BLay = typename CondLay<B_COL>::type;

    for (int kt = 0; kt < KT; kt++) {
        if (kt < KT - 1) asm volatile("cp.async.wait_group %0;" :: "n"(NSTAGE - 2));
        else             asm volatile("cp.async.wait_group 0;");
        __syncthreads();

        if (kt + NSTAGE - 1 < KT)
            load_tiles((kt + NSTAGE - 1) % NSTAGE, (kt + NSTAGE - 1) * BK);
        asm volatile("cp.async.commit_group;");

        __half* sA = hm + (kt % NSTAGE) * STAGE;
        __half* sB = sA + A_ELEMS;

        #pragma unroll
        for (int kk = 0; kk < BK; kk += 16) {
            wmma::fragment<wmma::matrix_a, 16, 16, 16, __half, ALay> fa[4];
            wmma::fragment<wmma::matrix_b, 16, 16, 16, __half, BLay> fb[4];
            #pragma unroll
            for (int im = 0; im < 4; im++) {
                int m0 = wm * 64 + im * 16;
                const __half* p = A_COL ? (sA + kk * 136 + m0) : (sA + m0 * 40 + kk);
                wmma::load_matrix_sync(fa[im], p, A_COL ? 136 : 40);
            }
            #pragma unroll
            for (int in_ = 0; in_ < 4; in_++) {
                int n0 = wn * 64 + in_ * 16;
                const __half* p = B_COL ? (sB + n0 * 40 + kk) : (sB + kk * 264 + n0);
                wmma::load_matrix_sync(fb[in_], p, B_COL ? 40 : 264);
            }
            #pragma unroll
            for (int im = 0; im < 4; im++)
                #pragma unroll
                for (int in_ = 0; in_ < 4; in_++)
                    wmma::mma_sync(acc[im][in_], fa[im], fb[in_], acc[im][in_]);
        }
    }
    __syncthreads();   // pipeline buffers free for epilogue staging

    // ---- epilogue: two n-halves of 128 cols via smem [128][132] f32 ----
    float* sC = (float*)smem_raw;
    #pragma unroll
    for (int half = 0; half < 2; half++) {
        if (half > 0) __syncthreads();
        if ((wn >> 1) == half) {
            int nloc = (wn & 1) * 64;
            #pragma unroll
            for (int im = 0; im < 4; im++)
                #pragma unroll
                for (int in_ = 0; in_ < 4; in_++)
                    wmma::store_matrix_sync(sC + (wm * 64 + im * 16) * 132 + nloc + in_ * 16,
                                            acc[im][in_], 132, wmma::mem_row_major);
        }
        __syncthreads();

        #pragma unroll
        for (int i = tid; i < 128 * 32; i += 256) {
            int m = i >> 5, n4 = (i & 31) << 2;
            int gn = bn + half * 128 + n4;
            float4 v;
            v.x = alpha * sC[m * 132 + n4 + 0];
            v.y = alpha * sC[m * 132 + n4 + 1];
            v.z = alpha * sC[m * 132 + n4 + 2];
            v.w = alpha * sC[m * 132 + n4 + 3];
            if (HAS_BIAS) {
                float bb = bias[bm + m];
                v.x += bb; v.y += bb; v.z += bb; v.w += bb;
            }
            if (HAS_RES) {
                const float4 r = *(const float4*)&res[(size_t)(bm + m) * LDC + gn];
                v.x += r.x; v.y += r.y; v.z += r.z; v.w += r.w;
            }
            if (OUT_HALF) {
                __half* Ch = (__half*)Cv + (size_t)bz * strC;
                __half2 h0 = __floats2half2_rn(v.x, v.y);
                __half2 h1 = __floats2half2_rn(v.z, v.w);
                uint2 pk = { *(uint32_t*)&h0, *(uint32_t*)&h1 };
                *(uint2*)&Ch[(size_t)(bm + m) * LDC + gn] = pk;
            } else {
                float* Cf = (float*)Cv + (size_t)bz * strC;
                *(float4*)&Cf[(size_t)(bm + m) * LDC + gn] = v;
            }
        }
    }
}

// ---------------- softmax: register-resident, fp32 in -> fp16 out ----------------
__global__ void __launch_bounds__(512)
softmax_kernel(const float* __restrict__ S, __half* __restrict__ P) {
    const float* row = S + (size_t)blockIdx.x * AREA;
    __half* prow = P + (size_t)blockIdx.x * AREA;
    const int tid = threadIdx.x;
    const int lane = tid & 31, wid = tid >> 5;
    __shared__ float red[16];

    // load 8 consecutive floats per thread
    float4 a = *(const float4*)&row[tid * 8];
    float4 b = *(const float4*)&row[tid * 8 + 4];

    float m = fmaxf(fmaxf(fmaxf(a.x, a.y), fmaxf(a.z, a.w)),
                    fmaxf(fmaxf(b.x, b.y), fmaxf(b.z, b.w)));
    #pragma unroll
    for (int o = 16; o > 0; o >>= 1)
        m = fmaxf(m, __shfl_xor_sync(0xFFFFFFFF, m, o));
    if (lane == 0) red[wid] = m;
    __syncthreads();
    if (wid == 0) {
        float t = red[lane & 15];
        #pragma unroll
        for (int o = 8; o > 0; o >>= 1)
            t = fmaxf(t, __shfl_xor_sync(0xFFFFFFFF, t, o));
        red[lane & 15] = t;
    }
    __syncthreads();
    m = red[0];

    a.x = __expf(a.x - m); a.y = __expf(a.y - m);
    a.z = __expf(a.z - m); a.w = __expf(a.w - m);
    b.x = __expf(b.x - m); b.y = __expf(b.y - m);
    b.z = __expf(b.z - m); b.w = __expf(b.w - m);

    float s = a.x + a.y + a.z + a.w + b.x + b.y + b.z + b.w;
    #pragma unroll
    for (int o = 16; o > 0; o >>= 1)
        s += __shfl_xor_sync(0xFFFFFFFF, s, o);
    __syncthreads();
    if (lane == 0) red[wid] = s;
    __syncthreads();
    if (wid == 0) {
        float t = red[lane & 15];
        #pragma unroll
        for (int o = 8; o > 0; o >>= 1)
            t += __shfl_xor_sync(0xFFFFFFFF, t, o);
        red[lane & 15] = t;
    }
    __syncthreads();
    float inv = 1.0f / red[0];

    __half2 h0 = __floats2half2_rn(a.x * inv, a.y * inv);
    __half2 h1 = __floats2half2_rn(a.z * inv, a.w * inv);
    __half2 h2 = __floats2half2_rn(b.x * inv, b.y * inv);
    __half2 h3 = __floats2half2_rn(b.z * inv, b.w * inv);
    uint4 pk = { *(uint32_t*)&h0, *(uint32_t*)&h1, *(uint32_t*)&h2, *(uint32_t*)&h3 };
    *(uint4*)&prow[tid * 8] = pk;
}

// ---------------- launch ----------------
extern "C" void kernel_launch(void* const* d_in, const int* in_sizes, int n_in,
                              void* d_out, int out_size) {
    const float* net      = (const float*)d_in[0];
    const float* gn_scale = (const float*)d_in[1];
    const float* gn_bias  = (const float*)d_in[2];
    const float* wq = (const float*)d_in[3];
    const float* bq = (const float*)d_in[4];
    const float* wk = (const float*)d_in[5];
    const float* bk = (const float*)d_in[6];
    const float* wv = (const float*)d_in[7];
    const float* bv = (const float*)d_in[8];
    const float* wo = (const float*)d_in[9];
    const float* bo = (const float*)d_in[10];
    float* out = (float*)d_out;

    __half *xn, *qkv, *h, *p, *wqkv, *woh;
    float *s, *bqkv;
    cudaGetSymbolAddress((void**)&xn,   g_xn);
    cudaGetSymbolAddress((void**)&qkv,  g_qkv);
    cudaGetSymbolAddress((void**)&h,    g_h);
    cudaGetSymbolAddress((void**)&s,    g_s);
    cudaGetSymbolAddress((void**)&p,    g_p);
    cudaGetSymbolAddress((void**)&wqkv, g_wqkv);
    cudaGetSymbolAddress((void**)&woh,  g_wo);
    cudaGetSymbolAddress((void**)&bqkv, g_bqkv);

    auto kQKV = gemm_fp16<CCH,  CCH,  AREA, AREA, false, false, true,  false, true >;
    auto kSC  = gemm_fp16<CCH,  AREA, AREA, AREA, true,  false, false, false, false>;
    auto kPV  = gemm_fp16<AREA, AREA, AREA, AREA, false, true,  false, false, true >;
    auto kOUT = gemm_fp16<CCH,  CCH,  AREA, AREA, false, false, true,  true,  false>;

    const int SM_FF = SmemSize<false, false>::BYTES;
    const int SM_TF = SmemSize<true,  false>::BYTES;
    const int SM_FT = SmemSize<false, true >::BYTES;

    cudaFuncSetAttribute(kQKV, cudaFuncAttributeMaxDynamicSharedMemorySize, SM_FF);
    cudaFuncSetAttribute(kSC,  cudaFuncAttributeMaxDynamicSharedMemorySize, SM_TF);
    cudaFuncSetAttribute(kPV,  cudaFuncAttributeMaxDynamicSharedMemorySize, SM_FT);
    cudaFuncSetAttribute(kOUT, cudaFuncAttributeMaxDynamicSharedMemorySize, SM_FF);

    const long sBC  = (long)CCH * AREA;
    const long s3BC = (long)3 * CCH * AREA;
    const long sSS  = (long)AREA * AREA;
    const float inv_sqrt_c = 1.0f / sqrtf((float)CCH);

    pack_kernel<<<(CCH * CCH + 255) / 256, 256>>>(wq, wk, wv, wo, bq, bk, bv,
                                                  wqkv, woh, bqkv);
    groupnorm_kernel<<<BATCH * GRP, 256>>>(net, gn_scale, gn_bias, xn);

    // QKV = Wqkv @ xn + b  (M=1536, N=4096, K=512), half out
    {
        dim3 g(AREA / BN, (3 * CCH) / BM, BATCH);   // (16, 12, 4)
        kQKV<<<g, 256, SM_FF>>>(wqkv, xn, qkv, bqkv, nullptr, 0, sBC, s3BC, 0, 1.0f);
    }

    const __half* q = qkv;
    const __half* k = qkv + (size_t)CCH * AREA;
    const __half* v = qkv + (size_t)2 * CCH * AREA;

    // S = (Q^T K) / sqrt(C), fp32 out
    {
        dim3 g(AREA / BN, AREA / BM, BATCH);        // (16, 32, 4)
        kSC<<<g, 256, SM_TF>>>(q, k, s, nullptr, nullptr, s3BC, s3BC, sSS, 0, inv_sqrt_c);
    }

    softmax_kernel<<<BATCH * AREA, 512>>>(s, p);

    // H = V @ P^T, half out
    {
        dim3 g(AREA / BN, CCH / BM, BATCH);         // (16, 4, 4)
        kPV<<<g, 256, SM_FT>>>(v, p, h, nullptr, nullptr, s3BC, sSS, sBC, 0, 1.0f);
    }

    // out = net + Wo @ H + bo, fp32 out
    {
        dim3 g(AREA / BN, CCH / BM, BATCH);         // (16, 4, 4)
        kOUT<<<g, 256, SM_FF>>>(woh, h, out, bo, net, 0, sBC, sBC, sBC, 1.0f);
    }
}

// round 15
// speedup vs baseline: 1.1563x; 1.1563x over previous
#include <cuda_runtime.h>
#include <cuda_fp16.h>
#include <cstdint>
#include <mma.h>
#include <math.h>

using namespace nvcuda;

#define CCH 512
#define GRP 32
#define AREA 4096
#define BATCH 4
#define EPS 1e-6f

// ---------------- scratch (device globals) ----------------
__device__ __half g_xn  [(size_t)BATCH * CCH * AREA];
__device__ __half g_qkv [(size_t)BATCH * 3 * CCH * AREA];
__device__ __half g_h   [(size_t)BATCH * CCH * AREA];
__device__ float  g_s   [(size_t)BATCH * AREA * AREA];
__device__ __half g_p   [(size_t)BATCH * AREA * AREA];
__device__ __half g_wqkv[3 * CCH * CCH];
__device__ __half g_wo  [CCH * CCH];
__device__ float  g_bqkv[3 * CCH];

// ---------------- GroupNorm -> half output ----------------
__global__ void groupnorm_kernel(const float* __restrict__ net,
                                 const float* __restrict__ gscale,
                                 const float* __restrict__ gbias,
                                 __half* __restrict__ xn) {
    const int CPG = CCH / GRP;
    const int NEL = CPG * AREA;
    int bg = blockIdx.x;
    int b = bg / GRP, g = bg % GRP;
    const float* x = net + ((size_t)b * CCH + (size_t)g * CPG) * AREA;
    __half* y = xn + ((size_t)b * CCH + (size_t)g * CPG) * AREA;

    int tid = threadIdx.x;
    float s = 0.f, ss = 0.f;
    for (int i = tid; i < NEL; i += blockDim.x) {
        float v = x[i];
        s += v; ss += v * v;
    }
    __shared__ float rs[256], rss[256];
    rs[tid] = s; rss[tid] = ss;
    __syncthreads();
    for (int o = 128; o > 0; o >>= 1) {
        if (tid < o) { rs[tid] += rs[tid + o]; rss[tid] += rss[tid + o]; }
        __syncthreads();
    }
    float mu  = rs[0] / (float)NEL;
    float var = rss[0] / (float)NEL - mu * mu;
    float inv = rsqrtf(var + EPS);

    for (int i = tid; i < NEL; i += blockDim.x) {
        int cl = i / AREA;
        int c  = g * CPG + cl;
        y[i] = __float2half((x[i] - mu) * inv * gscale[c] + gbias[c]);
    }
}

// ---------------- pack weights -> half ----------------
__global__ void pack_kernel(const float* __restrict__ wq, const float* __restrict__ wk,
                            const float* __restrict__ wv, const float* __restrict__ wo,
                            const float* __restrict__ bq, const float* __restrict__ bk,
                            const float* __restrict__ bv,
                            __half* __restrict__ w, __half* __restrict__ woh,
                            float* __restrict__ b) {
    int i = blockIdx.x * blockDim.x + threadIdx.x;
    const int WN = CCH * CCH;
    if (i < WN) {
        w[i]          = __float2half(wq[i]);
        w[i + WN]     = __float2half(wk[i]);
        w[i + 2 * WN] = __float2half(wv[i]);
        woh[i]        = __float2half(wo[i]);
    }
    if (i < CCH) {
        b[i] = bq[i];
        b[i + CCH] = bk[i];
        b[i + 2 * CCH] = bv[i];
    }
}

// ---------------- 3-stage cp.async FP16 WMMA GEMM, 128x128x64 ----------------
// D[m,n] = alpha*sum_k A(m,k)*B(k,n) [+bias[m]] [+res], fp32 accumulate.
// A_COL: A(m,k)=A[k*LDA+m]; B_COL: B(k,n)=B[n*LDB+k]. OUT_HALF: C half else float.
#define BM 128
#define BN 128
#define BK 64
#define NSTAGE 3

template<bool C_> struct CondLay;
template<> struct CondLay<false> { using type = wmma::row_major; };
template<> struct CondLay<true>  { using type = wmma::col_major; };

__device__ __forceinline__ void cp16(void* s, const void* g) {
    unsigned int sa = (unsigned int)__cvta_generic_to_shared(s);
    asm volatile("cp.async.cg.shared.global [%0], [%1], 16;" :: "r"(sa), "l"(g));
}

template<bool A_COL, bool B_COL>
struct SmemSize {
    static constexpr int A_ELEMS = A_COL ? BK * 136 : BM * 72;   // halves
    static constexpr int B_ELEMS = B_COL ? BN * 72  : BK * 136;  // halves
    static constexpr int STAGE   = A_ELEMS + B_ELEMS;
    static constexpr int BYTES_PIPE = NSTAGE * STAGE * 2;
    static constexpr int BYTES_EPI  = 128 * 132 * 4;
    static constexpr int BYTES = BYTES_PIPE > BYTES_EPI ? BYTES_PIPE : BYTES_EPI;
};

template<int Kv, int LDA, int LDB, int LDC,
         bool A_COL, bool B_COL, bool HAS_BIAS, bool HAS_RES, bool OUT_HALF>
__global__ void __launch_bounds__(256, 2)
gemm_fp16(const __half* __restrict__ A, const __half* __restrict__ B,
          void* __restrict__ Cv,
          const float* __restrict__ bias, const float* __restrict__ res,
          long strA, long strB, long strC, long strR, float alpha) {
    extern __shared__ __align__(16) char smem_raw[];
    __half* hm = (__half*)smem_raw;
    constexpr int A_ELEMS = SmemSize<A_COL, B_COL>::A_ELEMS;
    constexpr int STAGE   = SmemSize<A_COL, B_COL>::STAGE;
    constexpr int KT      = Kv / BK;

    const int bz = blockIdx.z;
    A += (size_t)bz * strA;
    B += (size_t)bz * strB;
    if (HAS_RES) res += (size_t)bz * strR;

    const int bm = blockIdx.y * BM;
    const int bn = blockIdx.x * BN;
    const int tid = threadIdx.x;
    const int warp = tid >> 5;
    const int wm = warp >> 1;    // 0..3
    const int wn = warp & 1;     // 0..1

    wmma::fragment<wmma::accumulator, 16, 16, 16, float> acc[2][4];
    #pragma unroll
    for (int i = 0; i < 2; i++)
        #pragma unroll
        for (int j = 0; j < 4; j++)
            wmma::fill_fragment(acc[i][j], 0.0f);

    auto load_tiles = [&](int slot, int k0) {
        __half* sA = hm + slot * STAGE;
        __half* sB = sA + A_ELEMS;
        if (A_COL) {
            #pragma unroll
            for (int c = tid; c < 1024; c += 256) {
                int k = c >> 4, m8 = (c & 15) << 3;
                cp16(&sA[k * 136 + m8], &A[(size_t)(k0 + k) * LDA + bm + m8]);
            }
        } else {
            #pragma unroll
            for (int c = tid; c < 1024; c += 256) {
                int m = c >> 3, k8 = (c & 7) << 3;
                cp16(&sA[m * 72 + k8], &A[(size_t)(bm + m) * LDA + k0 + k8]);
            }
        }
        if (B_COL) {
            #pragma unroll
            for (int c = tid; c < 1024; c += 256) {
                int n = c >> 3, k8 = (c & 7) << 3;
                cp16(&sB[n * 72 + k8], &B[(size_t)(bn + n) * LDB + k0 + k8]);
            }
        } else {
            #pragma unroll
            for (int c = tid; c < 1024; c += 256) {
                int k = c >> 4, n8 = (c & 15) << 3;
                cp16(&sB[k * 136 + n8], &B[(size_t)(k0 + k) * LDB + bn + n8]);
            }
        }
    };

    #pragma unroll
    for (int s = 0; s < NSTAGE - 1; s++) {
        if (s < KT) load_tiles(s, s * BK);
        asm volatile("cp.async.commit_group;");
    }

    using ALay = typename CondLay<A_COL>::type;
    using BLay = typename CondLay<B_COL>::type;

    for (int kt = 0; kt < KT; kt++) {
        if (kt < KT - 1) asm volatile("cp.async.wait_group %0;" :: "n"(NSTAGE - 2));
        else             asm volatile("cp.async.wait_group 0;");
        __syncthreads();

        if (kt + NSTAGE - 1 < KT)
            load_tiles((kt + NSTAGE - 1) % NSTAGE, (kt + NSTAGE - 1) * BK);
        asm volatile("cp.async.commit_group;");

        __half* sA = hm + (kt % NSTAGE) * STAGE;
        __half* sB = sA + A_ELEMS;

        #pragma unroll
        for (int kk = 0; kk < BK; kk += 16) {
            wmma::fragment<wmma::matrix_a, 16, 16, 16, __half, ALay> fa[2];
            wmma::fragment<wmma::matrix_b, 16, 16, 16, __half, BLay> fb[4];
            #pragma unroll
            for (int im = 0; im < 2; im++) {
                int m0 = wm * 32 + im * 16;
                const __half* p = A_COL ? (sA + kk * 136 + m0) : (sA + m0 * 72 + kk);
                wmma::load_matrix_sync(fa[im], p, A_COL ? 136 : 72);
            }
            #pragma unroll
            for (int in_ = 0; in_ < 4; in_++) {
                int n0 = wn * 64 + in_ * 16;
                const __half* p = B_COL ? (sB + n0 * 72 + kk) : (sB + kk * 136 + n0);
                wmma::load_matrix_sync(fb[in_], p, B_COL ? 72 : 136);
            }
            #pragma unroll
            for (int im = 0; im < 2; im++)
                #pragma unroll
                for (int in_ = 0; in_ < 4; in_++)
                    wmma::mma_sync(acc[im][in_], fa[im], fb[in_], acc[im][in_]);
        }
    }
    __syncthreads();

    // ---- epilogue: stage accums in smem (fp32), then write ----
    float* sC = (float*)smem_raw;   // [128][132]
    #pragma unroll
    for (int im = 0; im < 2; im++)
        #pragma unroll
        for (int in_ = 0; in_ < 4; in_++)
            wmma::store_matrix_sync(sC + (wm * 32 + im * 16) * 132 + wn * 64 + in_ * 16,
                                    acc[im][in_], 132, wmma::mem_row_major);
    __syncthreads();

    #pragma unroll
    for (int i = tid; i < BM * BN / 4; i += 256) {
        int m = i >> 5, n4 = (i & 31) << 2;
        float4 v;
        v.x = alpha * sC[m * 132 + n4 + 0];
        v.y = alpha * sC[m * 132 + n4 + 1];
        v.z = alpha * sC[m * 132 + n4 + 2];
        v.w = alpha * sC[m * 132 + n4 + 3];
        if (HAS_BIAS) {
            float bb = bias[bm + m];
            v.x += bb; v.y += bb; v.z += bb; v.w += bb;
        }
        if (HAS_RES) {
            const float4 r = *(const float4*)&res[(size_t)(bm + m) * LDC + bn + n4];
            v.x += r.x; v.y += r.y; v.z += r.z; v.w += r.w;
        }
        if (OUT_HALF) {
            __half* Ch = (__half*)Cv + (size_t)bz * strC;
            __half2 h0 = __floats2half2_rn(v.x, v.y);
            __half2 h1 = __floats2half2_rn(v.z, v.w);
            uint2 pk = { *(uint32_t*)&h0, *(uint32_t*)&h1 };
            *(uint2*)&Ch[(size_t)(bm + m) * LDC + bn + n4] = pk;
        } else {
            float* Cf = (float*)Cv + (size_t)bz * strC;
            *(float4*)&Cf[(size_t)(bm + m) * LDC + bn + n4] = v;
        }
    }
}

// ---------------- softmax: register-resident, fp32 in -> fp16 out ----------------
__global__ void __launch_bounds__(512)
softmax_kernel(const float* __restrict__ S, __half* __restrict__ P) {
    const float* row = S + (size_t)blockIdx.x * AREA;
    __half* prow = P + (size_t)blockIdx.x * AREA;
    const int tid = threadIdx.x;
    const int lane = tid & 31, wid = tid >> 5;
    __shared__ float red[16];

    float4 a = *(const float4*)&row[tid * 8];
    float4 b = *(const float4*)&row[tid * 8 + 4];

    float m = fmaxf(fmaxf(fmaxf(a.x, a.y), fmaxf(a.z, a.w)),
                    fmaxf(fmaxf(b.x, b.y), fmaxf(b.z, b.w)));
    #pragma unroll
    for (int o = 16; o > 0; o >>= 1)
        m = fmaxf(m, __shfl_xor_sync(0xFFFFFFFF, m, o));
    if (lane == 0) red[wid] = m;
    __syncthreads();
    if (wid == 0) {
        float t = red[lane & 15];
        #pragma unroll
        for (int o = 8; o > 0; o >>= 1)
            t = fmaxf(t, __shfl_xor_sync(0xFFFFFFFF, t, o));
        red[lane & 15] = t;
    }
    __syncthreads();
    m = red[0];

    a.x = __expf(a.x - m); a.y = __expf(a.y - m);
    a.z = __expf(a.z - m); a.w = __expf(a.w - m);
    b.x = __expf(b.x - m); b.y = __expf(b.y - m);
    b.z = __expf(b.z - m); b.w = __expf(b.w - m);

    float s = a.x + a.y + a.z + a.w + b.x + b.y + b.z + b.w;
    #pragma unroll
    for (int o = 16; o > 0; o >>= 1)
        s += __shfl_xor_sync(0xFFFFFFFF, s, o);
    __syncthreads();
    if (lane == 0) red[wid] = s;
    __syncthreads();
    if (wid == 0) {
        float t = red[lane & 15];
        #pragma unroll
        for (int o = 8; o > 0; o >>= 1)
            t += __shfl_xor_sync(0xFFFFFFFF, t, o);
        red[lane & 15] = t;
    }
    __syncthreads();
    float inv = 1.0f / red[0];

    __half2 h0 = __floats2half2_rn(a.x * inv, a.y * inv);
    __half2 h1 = __floats2half2_rn(a.z * inv, a.w * inv);
    __half2 h2 = __floats2half2_rn(b.x * inv, b.y * inv);
    __half2 h3 = __floats2half2_rn(b.z * inv, b.w * inv);
    uint4 pk = { *(uint32_t*)&h0, *(uint32_t*)&h1, *(uint32_t*)&h2, *(uint32_t*)&h3 };
    *(uint4*)&prow[tid * 8] = pk;
}

// ---------------- launch ----------------
extern "C" void kernel_launch(void* const* d_in, const int* in_sizes, int n_in,
                              void* d_out, int out_size) {
    const float* net      = (const float*)d_in[0];
    const float* gn_scale = (const float*)d_in[1];
    const float* gn_bias  = (const float*)d_in[2];
    const float* wq = (const float*)d_in[3];
    const float* bq = (const float*)d_in[4];
    const float* wk = (const float*)d_in[5];
    const float* bk = (const float*)d_in[6];
    const float* wv = (const float*)d_in[7];
    const float* bv = (const float*)d_in[8];
    const float* wo = (const float*)d_in[9];
    const float* bo = (const float*)d_in[10];
    float* out = (float*)d_out;

    __half *xn, *qkv, *h, *p, *wqkv, *woh;
    float *s, *bqkv;
    cudaGetSymbolAddress((void**)&xn,   g_xn);
    cudaGetSymbolAddress((void**)&qkv,  g_qkv);
    cudaGetSymbolAddress((void**)&h,    g_h);
    cudaGetSymbolAddress((void**)&s,    g_s);
    cudaGetSymbolAddress((void**)&p,    g_p);
    cudaGetSymbolAddress((void**)&wqkv, g_wqkv);
    cudaGetSymbolAddress((void**)&woh,  g_wo);
    cudaGetSymbolAddress((void**)&bqkv, g_bqkv);

    auto kQKV = gemm_fp16<CCH,  CCH,  AREA, AREA, false, false, true,  false, true >;
    auto kSC  = gemm_fp16<CCH,  AREA, AREA, AREA, true,  false, false, false, false>;
    auto kPV  = gemm_fp16<AREA, AREA, AREA, AREA, false, true,  false, false, true >;
    auto kOUT = gemm_fp16<CCH,  CCH,  AREA, AREA, false, false, true,  true,  false>;

    const int SM_FF = SmemSize<false, false>::BYTES;
    const int SM_TF = SmemSize<true,  false>::BYTES;
    const int SM_FT = SmemSize<false, true >::BYTES;

    cudaFuncSetAttribute(kQKV, cudaFuncAttributeMaxDynamicSharedMemorySize, SM_FF);
    cudaFuncSetAttribute(kSC,  cudaFuncAttributeMaxDynamicSharedMemorySize, SM_TF);
    cudaFuncSetAttribute(kPV,  cudaFuncAttributeMaxDynamicSharedMemorySize, SM_FT);
    cudaFuncSetAttribute(kOUT, cudaFuncAttributeMaxDynamicSharedMemorySize, SM_FF);

    const long sBC  = (long)CCH * AREA;
    const long s3BC = (long)3 * CCH * AREA;
    const long sSS  = (long)AREA * AREA;
    const float inv_sqrt_c = 1.0f / sqrtf((float)CCH);

    pack_kernel<<<(CCH * CCH + 255) / 256, 256>>>(wq, wk, wv, wo, bq, bk, bv,
                                                  wqkv, woh, bqkv);
    groupnorm_kernel<<<BATCH * GRP, 256>>>(net, gn_scale, gn_bias, xn);

    // QKV = Wqkv @ xn + b  (M=1536, N=4096, K=512), half out
    {
        dim3 g(AREA / BN, (3 * CCH) / BM, BATCH);   // (32, 12, 4)
        kQKV<<<g, 256, SM_FF>>>(wqkv, xn, qkv, bqkv, nullptr, 0, sBC, s3BC, 0, 1.0f);
    }

    const __half* q = qkv;
    const __half* k = qkv + (size_t)CCH * AREA;
    const __half* v = qkv + (size_t)2 * CCH * AREA;

    // S = (Q^T K) / sqrt(C), fp32 out
    {
        dim3 g(AREA / BN, AREA / BM, BATCH);        // (32, 32, 4)
        kSC<<<g, 256, SM_TF>>>(q, k, s, nullptr, nullptr, s3BC, s3BC, sSS, 0, inv_sqrt_c);
    }

    softmax_kernel<<<BATCH * AREA, 512>>>(s, p);

    // H = V @ P^T, half out
    {
        dim3 g(AREA / BN, CCH / BM, BATCH);         // (32, 4, 4)
        kPV<<<g, 256, SM_FT>>>(v, p, h, nullptr, nullptr, s3BC, sSS, sBC, 0, 1.0f);
    }

    // out = net + Wo @ H + bo, fp32 out
    {
        dim3 g(AREA / BN, CCH / BM, BATCH);         // (32, 4, 4)
        kOUT<<<g, 256, SM_FF>>>(woh, h, out, bo, net, 0, sBC, sBC, sBC, 1.0f);
    }
}

// round 16
// speedup vs baseline: 1.1985x; 1.0364x over previous
#include <cuda_runtime.h>
#include <cuda_fp16.h>
#include <cstdint>
#include <mma.h>
#include <math.h>

using namespace nvcuda;

#define CCH 512
#define GRP 32
#define AREA 4096
#define BATCH 4
#define EPS 1e-6f

// ---------------- scratch (device globals) ----------------
__device__ __half g_xn  [(size_t)BATCH * CCH * AREA];
__device__ __half g_qkv [(size_t)BATCH * 3 * CCH * AREA];
__device__ __half g_h   [(size_t)BATCH * CCH * AREA];
__device__ __half g_s   [(size_t)BATCH * AREA * AREA];   // 128 MB scores (fp16)
__device__ __half g_p   [(size_t)BATCH * AREA * AREA];   // 128 MB probs (fp16)
__device__ __half g_wqkv[3 * CCH * CCH];
__device__ __half g_wo  [CCH * CCH];
__device__ float  g_bqkv[3 * CCH];

// ---------------- GroupNorm -> half output ----------------
__global__ void groupnorm_kernel(const float* __restrict__ net,
                                 const float* __restrict__ gscale,
                                 const float* __restrict__ gbias,
                                 __half* __restrict__ xn) {
    const int CPG = CCH / GRP;
    const int NEL = CPG * AREA;
    int bg = blockIdx.x;
    int b = bg / GRP, g = bg % GRP;
    const float* x = net + ((size_t)b * CCH + (size_t)g * CPG) * AREA;
    __half* y = xn + ((size_t)b * CCH + (size_t)g * CPG) * AREA;

    int tid = threadIdx.x;
    float s = 0.f, ss = 0.f;
    for (int i = tid; i < NEL; i += blockDim.x) {
        float v = x[i];
        s += v; ss += v * v;
    }
    __shared__ float rs[256], rss[256];
    rs[tid] = s; rss[tid] = ss;
    __syncthreads();
    for (int o = 128; o > 0; o >>= 1) {
        if (tid < o) { rs[tid] += rs[tid + o]; rss[tid] += rss[tid + o]; }
        __syncthreads();
    }
    float mu  = rs[0] / (float)NEL;
    float var = rss[0] / (float)NEL - mu * mu;
    float inv = rsqrtf(var + EPS);

    for (int i = tid; i < NEL; i += blockDim.x) {
        int cl = i / AREA;
        int c  = g * CPG + cl;
        y[i] = __float2half((x[i] - mu) * inv * gscale[c] + gbias[c]);
    }
}

// ---------------- pack weights -> half ----------------
__global__ void pack_kernel(const float* __restrict__ wq, const float* __restrict__ wk,
                            const float* __restrict__ wv, const float* __restrict__ wo,
                            const float* __restrict__ bq, const float* __restrict__ bk,
                            const float* __restrict__ bv,
                            __half* __restrict__ w, __half* __restrict__ woh,
                            float* __restrict__ b) {
    int i = blockIdx.x * blockDim.x + threadIdx.x;
    const int WN = CCH * CCH;
    if (i < WN) {
        w[i]          = __float2half(wq[i]);
        w[i + WN]     = __float2half(wk[i]);
        w[i + 2 * WN] = __float2half(wv[i]);
        woh[i]        = __float2half(wo[i]);
    }
    if (i < CCH) {
        b[i] = bq[i];
        b[i + CCH] = bk[i];
        b[i + 2 * CCH] = bv[i];
    }
}

// ---------------- 3-stage cp.async FP16 WMMA GEMM, 128x128x64 ----------------
// D[m,n] = alpha*sum_k A(m,k)*B(k,n) [+bias[m]] [+res], fp32 accumulate.
// A_COL: A(m,k)=A[k*LDA+m]; B_COL: B(k,n)=B[n*LDB+k]. OUT_HALF: C half else float.
#define BM 128
#define BN 128
#define BK 64
#define NSTAGE 3

template<bool C_> struct CondLay;
template<> struct CondLay<false> { using type = wmma::row_major; };
template<> struct CondLay<true>  { using type = wmma::col_major; };

__device__ __forceinline__ void cp16(void* s, const void* g) {
    unsigned int sa = (unsigned int)__cvta_generic_to_shared(s);
    asm volatile("cp.async.cg.shared.global [%0], [%1], 16;" :: "r"(sa), "l"(g));
}

template<bool A_COL, bool B_COL>
struct SmemSize {
    static constexpr int A_ELEMS = A_COL ? BK * 136 : BM * 72;   // halves
    static constexpr int B_ELEMS = B_COL ? BN * 72  : BK * 136;  // halves
    static constexpr int STAGE   = A_ELEMS + B_ELEMS;
    static constexpr int BYTES_PIPE = NSTAGE * STAGE * 2;
    static constexpr int BYTES_EPI  = 128 * 132 * 4;
    static constexpr int BYTES = BYTES_PIPE > BYTES_EPI ? BYTES_PIPE : BYTES_EPI;
};

template<int Kv, int LDA, int LDB, int LDC,
         bool A_COL, bool B_COL, bool HAS_BIAS, bool HAS_RES, bool OUT_HALF>
__global__ void __launch_bounds__(256, 2)
gemm_fp16(const __half* __restrict__ A, const __half* __restrict__ B,
          void* __restrict__ Cv,
          const float* __restrict__ bias, const float* __restrict__ res,
          long strA, long strB, long strC, long strR, float alpha) {
    extern __shared__ __align__(16) char smem_raw[];
    __half* hm = (__half*)smem_raw;
    constexpr int A_ELEMS = SmemSize<A_COL, B_COL>::A_ELEMS;
    constexpr int STAGE   = SmemSize<A_COL, B_COL>::STAGE;
    constexpr int KT      = Kv / BK;

    const int bz = blockIdx.z;
    A += (size_t)bz * strA;
    B += (size_t)bz * strB;
    if (HAS_RES) res += (size_t)bz * strR;

    const int bm = blockIdx.y * BM;
    const int bn = blockIdx.x * BN;
    const int tid = threadIdx.x;
    const int warp = tid >> 5;
    const int wm = warp >> 1;    // 0..3
    const int wn = warp & 1;     // 0..1

    wmma::fragment<wmma::accumulator, 16, 16, 16, float> acc[2][4];
    #pragma unroll
    for (int i = 0; i < 2; i++)
        #pragma unroll
        for (int j = 0; j < 4; j++)
            wmma::fill_fragment(acc[i][j], 0.0f);

    auto load_tiles = [&](int slot, int k0) {
        __half* sA = hm + slot * STAGE;
        __half* sB = sA + A_ELEMS;
        if (A_COL) {
            #pragma unroll
            for (int c = tid; c < 1024; c += 256) {
                int k = c >> 4, m8 = (c & 15) << 3;
                cp16(&sA[k * 136 + m8], &A[(size_t)(k0 + k) * LDA + bm + m8]);
            }
        } else {
            #pragma unroll
            for (int c = tid; c < 1024; c += 256) {
                int m = c >> 3, k8 = (c & 7) << 3;
                cp16(&sA[m * 72 + k8], &A[(size_t)(bm + m) * LDA + k0 + k8]);
            }
        }
        if (B_COL) {
            #pragma unroll
            for (int c = tid; c < 1024; c += 256) {
                int n = c >> 3, k8 = (c & 7) << 3;
                cp16(&sB[n * 72 + k8], &B[(size_t)(bn + n) * LDB + k0 + k8]);
            }
        } else {
            #pragma unroll
            for (int c = tid; c < 1024; c += 256) {
                int k = c >> 4, n8 = (c & 15) << 3;
                cp16(&sB[k * 136 + n8], &B[(size_t)(k0 + k) * LDB + bn + n8]);
            }
        }
    };

    #pragma unroll
    for (int s = 0; s < NSTAGE - 1; s++) {
        if (s < KT) load_tiles(s, s * BK);
        asm volatile("cp.async.commit_group;");
    }

    using ALay = typename CondLay<A_COL>::type;
    using BLay = typename CondLay<B_COL>::type;

    for (int kt = 0; kt < KT; kt++) {
        if (kt < KT - 1) asm volatile("cp.async.wait_group %0;" :: "n"(NSTAGE - 2));
        else             asm volatile("cp.async.wait_group 0;");
        __syncthreads();

        if (kt + NSTAGE - 1 < KT)
            load_tiles((kt + NSTAGE - 1) % NSTAGE, (kt + NSTAGE - 1) * BK);
        asm volatile("cp.async.commit_group;");

        __half* sA = hm + (kt % NSTAGE) * STAGE;
        __half* sB = sA + A_ELEMS;

        #pragma unroll
        for (int kk = 0; kk < BK; kk += 16) {
            wmma::fragment<wmma::matrix_a, 16, 16, 16, __half, ALay> fa[2];
            wmma::fragment<wmma::matrix_b, 16, 16, 16, __half, BLay> fb[4];
            #pragma unroll
            for (int im = 0; im < 2; im++) {
                int m0 = wm * 32 + im * 16;
                const __half* p = A_COL ? (sA + kk * 136 + m0) : (sA + m0 * 72 + kk);
                wmma::load_matrix_sync(fa[im], p, A_COL ? 136 : 72);
            }
            #pragma unroll
            for (int in_ = 0; in_ < 4; in_++) {
                int n0 = wn * 64 + in_ * 16;
                const __half* p = B_COL ? (sB + n0 * 72 + kk) : (sB + kk * 136 + n0);
                wmma::load_matrix_sync(fb[in_], p, B_COL ? 72 : 136);
            }
            #pragma unroll
            for (int im = 0; im < 2; im++)
                #pragma unroll
                for (int in_ = 0; in_ < 4; in_++)
                    wmma::mma_sync(acc[im][in_], fa[im], fb[in_], acc[im][in_]);
        }
    }
    __syncthreads();

    // ---- epilogue: stage accums in smem (fp32), then write ----
    float* sC = (float*)smem_raw;   // [128][132]
    #pragma unroll
    for (int im = 0; im < 2; im++)
        #pragma unroll
        for (int in_ = 0; in_ < 4; in_++)
            wmma::store_matrix_sync(sC + (wm * 32 + im * 16) * 132 + wn * 64 + in_ * 16,
                                    acc[im][in_], 132, wmma::mem_row_major);
    __syncthreads();

    #pragma unroll
    for (int i = tid; i < BM * BN / 4; i += 256) {
        int m = i >> 5, n4 = (i & 31) << 2;
        float4 v;
        v.x = alpha * sC[m * 132 + n4 + 0];
        v.y = alpha * sC[m * 132 + n4 + 1];
        v.z = alpha * sC[m * 132 + n4 + 2];
        v.w = alpha * sC[m * 132 + n4 + 3];
        if (HAS_BIAS) {
            float bb = bias[bm + m];
            v.x += bb; v.y += bb; v.z += bb; v.w += bb;
        }
        if (HAS_RES) {
            const float4 r = *(const float4*)&res[(size_t)(bm + m) * LDC + bn + n4];
            v.x += r.x; v.y += r.y; v.z += r.z; v.w += r.w;
        }
        if (OUT_HALF) {
            __half* Ch = (__half*)Cv + (size_t)bz * strC;
            __half2 h0 = __floats2half2_rn(v.x, v.y);
            __half2 h1 = __floats2half2_rn(v.z, v.w);
            uint2 pk = { *(uint32_t*)&h0, *(uint32_t*)&h1 };
            *(uint2*)&Ch[(size_t)(bm + m) * LDC + bn + n4] = pk;
        } else {
            float* Cf = (float*)Cv + (size_t)bz * strC;
            *(float4*)&Cf[(size_t)(bm + m) * LDC + bn + n4] = v;
        }
    }
}

// ---------------- softmax: fp16 in -> fp16 out, register-resident ----------------
__global__ void __launch_bounds__(512)
softmax_kernel(const __half* __restrict__ S, __half* __restrict__ P) {
    const __half* row = S + (size_t)blockIdx.x * AREA;
    __half* prow = P + (size_t)blockIdx.x * AREA;
    const int tid = threadIdx.x;
    const int lane = tid & 31, wid = tid >> 5;
    __shared__ float red[16];

    // load 8 consecutive halves per thread
    uint4 raw = *(const uint4*)&row[tid * 8];
    __half2 h[4] = { *(__half2*)&raw.x, *(__half2*)&raw.y,
                     *(__half2*)&raw.z, *(__half2*)&raw.w };
    float2 f[4];
    #pragma unroll
    for (int i = 0; i < 4; i++) f[i] = __half22float2(h[i]);

    float m = -INFINITY;
    #pragma unroll
    for (int i = 0; i < 4; i++) m = fmaxf(m, fmaxf(f[i].x, f[i].y));
    #pragma unroll
    for (int o = 16; o > 0; o >>= 1)
        m = fmaxf(m, __shfl_xor_sync(0xFFFFFFFF, m, o));
    if (lane == 0) red[wid] = m;
    __syncthreads();
    if (wid == 0) {
        float t = red[lane & 15];
        #pragma unroll
        for (int o = 8; o > 0; o >>= 1)
            t = fmaxf(t, __shfl_xor_sync(0xFFFFFFFF, t, o));
        red[lane & 15] = t;
    }
    __syncthreads();
    m = red[0];

    float s = 0.f;
    #pragma unroll
    for (int i = 0; i < 4; i++) {
        f[i].x = __expf(f[i].x - m);
        f[i].y = __expf(f[i].y - m);
        s += f[i].x + f[i].y;
    }
    #pragma unroll
    for (int o = 16; o > 0; o >>= 1)
        s += __shfl_xor_sync(0xFFFFFFFF, s, o);
    __syncthreads();
    if (lane == 0) red[wid] = s;
    __syncthreads();
    if (wid == 0) {
        float t = red[lane & 15];
        #pragma unroll
        for (int o = 8; o > 0; o >>= 1)
            t += __shfl_xor_sync(0xFFFFFFFF, t, o);
        red[lane & 15] = t;
    }
    __syncthreads();
    float inv = 1.0f / red[0];

    __half2 o0 = __floats2half2_rn(f[0].x * inv, f[0].y * inv);
    __half2 o1 = __floats2half2_rn(f[1].x * inv, f[1].y * inv);
    __half2 o2 = __floats2half2_rn(f[2].x * inv, f[2].y * inv);
    __half2 o3 = __floats2half2_rn(f[3].x * inv, f[3].y * inv);
    uint4 pk = { *(uint32_t*)&o0, *(uint32_t*)&o1, *(uint32_t*)&o2, *(uint32_t*)&o3 };
    *(uint4*)&prow[tid * 8] = pk;
}

// ---------------- launch ----------------
extern "C" void kernel_launch(void* const* d_in, const int* in_sizes, int n_in,
                              void* d_out, int out_size) {
    const float* net      = (const float*)d_in[0];
    const float* gn_scale = (const float*)d_in[1];
    const float* gn_bias  = (const float*)d_in[2];
    const float* wq = (const float*)d_in[3];
    const float* bq = (const float*)d_in[4];
    const float* wk = (const float*)d_in[5];
    const float* bk = (const float*)d_in[6];
    const float* wv = (const float*)d_in[7];
    const float* bv = (const float*)d_in[8];
    const float* wo = (const float*)d_in[9];
    const float* bo = (const float*)d_in[10];
    float* out = (float*)d_out;

    __half *xn, *qkv, *h, *sh, *p, *wqkv, *woh;
    float *bqkv;
    cudaGetSymbolAddress((void**)&xn,   g_xn);
    cudaGetSymbolAddress((void**)&qkv,  g_qkv);
    cudaGetSymbolAddress((void**)&h,    g_h);
    cudaGetSymbolAddress((void**)&sh,   g_s);
    cudaGetSymbolAddress((void**)&p,    g_p);
    cudaGetSymbolAddress((void**)&wqkv, g_wqkv);
    cudaGetSymbolAddress((void**)&woh,  g_wo);
    cudaGetSymbolAddress((void**)&bqkv, g_bqkv);

    auto kQKV = gemm_fp16<CCH,  CCH,  AREA, AREA, false, false, true,  false, true >;
    auto kSC  = gemm_fp16<CCH,  AREA, AREA, AREA, true,  false, false, false, true >;
    auto kPV  = gemm_fp16<AREA, AREA, AREA, AREA, false, true,  false, false, true >;
    auto kOUT = gemm_fp16<CCH,  CCH,  AREA, AREA, false, false, true,  true,  false>;

    const int SM_FF = SmemSize<false, false>::BYTES;
    const int SM_TF = SmemSize<true,  false>::BYTES;
    const int SM_FT = SmemSize<false, true >::BYTES;

    cudaFuncSetAttribute(kQKV, cudaFuncAttributeMaxDynamicSharedMemorySize, SM_FF);
    cudaFuncSetAttribute(kSC,  cudaFuncAttributeMaxDynamicSharedMemorySize, SM_TF);
    cudaFuncSetAttribute(kPV,  cudaFuncAttributeMaxDynamicSharedMemorySize, SM_FT);
    cudaFuncSetAttribute(kOUT, cudaFuncAttributeMaxDynamicSharedMemorySize, SM_FF);

    const long sBC  = (long)CCH * AREA;
    const long s3BC = (long)3 * CCH * AREA;
    const long sSS  = (long)AREA * AREA;
    const float inv_sqrt_c = 1.0f / sqrtf((float)CCH);

    pack_kernel<<<(CCH * CCH + 255) / 256, 256>>>(wq, wk, wv, wo, bq, bk, bv,
                                                  wqkv, woh, bqkv);
    groupnorm_kernel<<<BATCH * GRP, 256>>>(net, gn_scale, gn_bias, xn);

    // QKV = Wqkv @ xn + b  (M=1536, N=4096, K=512), half out
    {
        dim3 g(AREA / BN, (3 * CCH) / BM, BATCH);   // (32, 12, 4)
        kQKV<<<g, 256, SM_FF>>>(wqkv, xn, qkv, bqkv, nullptr, 0, sBC, s3BC, 0, 1.0f);
    }

    const __half* q = qkv;
    const __half* k = qkv + (size_t)CCH * AREA;
    const __half* v = qkv + (size_t)2 * CCH * AREA;

    // S = (Q^T K) / sqrt(C), fp16 out
    {
        dim3 g(AREA / BN, AREA / BM, BATCH);        // (32, 32, 4)
        kSC<<<g, 256, SM_TF>>>(q, k, sh, nullptr, nullptr, s3BC, s3BC, sSS, 0, inv_sqrt_c);
    }

    softmax_kernel<<<BATCH * AREA, 512>>>(sh, p);

    // H = V @ P^T, half out
    {
        dim3 g(AREA / BN, CCH / BM, BATCH);         // (32, 4, 4)
        kPV<<<g, 256, SM_FT>>>(v, p, h, nullptr, nullptr, s3BC, sSS, sBC, 0, 1.0f);
    }

    // out = net + Wo @ H + bo, fp32 out
    {
        dim3 g(AREA / BN, CCH / BM, BATCH);         // (32, 4, 4)
        kOUT<<<g, 256, SM_FF>>>(woh, h, out, bo, net, 0, sBC, sBC, sBC, 1.0f);
    }
}